// round 9
// baseline (speedup 1.0000x reference)
#include <cuda_runtime.h>

// Problem constants
#define B 32
#define S 2048
#define H 1024

// ---- split-softmax config ----
#define NSPLIT 16            // S-splits per batch
#define CH (S / NSPLIT)      // 128 rows per CTA
#define WARPS 4              // 128-thread CTAs
#define RPW (CH / WARPS)     // 32 rows per warp

// ---- q GEMV config ----
#define KSLICES 32
#define KCH (H / KSLICES)    // 32
#define BG 8

// Scratch (no cudaMalloc allowed)
__device__ float  g_qpart[KSLICES * B * H];          // 4 MB
__device__ float  g_q[B * H];                        // 128 KB
__device__ float4 g_pacc[B * NSPLIT * (H / 4)];      // 2 MB
__device__ float  g_ml[B * NSPLIT * 2];              // merged (M, L) per split

// ---------------------------------------------------------------------------
// Kernel 1: partial q[b,h] = sum_{k in slice} h_t[b,k] * W[k,h]
// grid (1, KSLICES=32, B/BG=4), 256 threads.
// ---------------------------------------------------------------------------
__global__ __launch_bounds__(256) void qpart_kernel(const float* __restrict__ h_t,
                                                    const float* __restrict__ W)
{
    __shared__ float hs[BG][KCH];
    const int tid = threadIdx.x;
    const int k0  = blockIdx.y * KCH;
    const int bg  = blockIdx.z;

    {   // BG*KCH = 256 floats, one per thread
        int j  = tid >> 5;
        int kk = tid & 31;
        hs[j][kk] = h_t[(bg * BG + j) * H + k0 + kk];
    }
    __syncthreads();

    float4 acc[BG];
    #pragma unroll
    for (int j = 0; j < BG; j++) acc[j] = make_float4(0.f, 0.f, 0.f, 0.f);

    const float4* wp = reinterpret_cast<const float4*>(W) + (size_t)k0 * 256 + tid;
    #pragma unroll
    for (int kk = 0; kk < KCH; kk++) {
        float4 w = wp[(size_t)kk * 256];
        #pragma unroll
        for (int j = 0; j < BG; j++) {
            float h = hs[j][kk];
            acc[j].x = fmaf(h, w.x, acc[j].x);
            acc[j].y = fmaf(h, w.y, acc[j].y);
            acc[j].z = fmaf(h, w.z, acc[j].z);
            acc[j].w = fmaf(h, w.w, acc[j].w);
        }
    }
    float4* qp = reinterpret_cast<float4*>(g_qpart);
    #pragma unroll
    for (int j = 0; j < BG; j++)
        qp[((size_t)blockIdx.y * B + bg * BG + j) * 256 + tid] = acc[j];
}

// ---------------------------------------------------------------------------
// Kernel 1b: q = sum over KSLICES partials. grid (128), 256 threads.
// ---------------------------------------------------------------------------
__global__ __launch_bounds__(256) void qreduce_kernel()
{
    const int idx = blockIdx.x * 256 + threadIdx.x;
    float v = 0.f;
    #pragma unroll
    for (int p = 0; p < KSLICES; p++)
        v += g_qpart[(size_t)p * (B * H) + idx];
    g_q[idx] = v;
}

// ---------------------------------------------------------------------------
// Kernel 2: warp-autonomous split (R7-benched version: 2 rows per iter,
// 16 LDG.128 batched at iteration start, no barriers in main loop).
// grid (NSPLIT, B), 128 threads.
// ---------------------------------------------------------------------------
__global__ void __launch_bounds__(128, 4) split_kernel(const float* __restrict__ cntx)
{
    __shared__ float  q_s[H];              // 4 KB
    __shared__ float4 accbuf[WARPS][256];  // 16 KB
    __shared__ float  mlbuf[WARPS][2];

    const int tid  = threadIdx.x;
    const int wid  = tid >> 5;
    const int lane = tid & 31;
    const int b    = blockIdx.y;
    const int sp   = blockIdx.x;

    float4* q_s4 = reinterpret_cast<float4*>(q_s);
    q_s4[tid]       = reinterpret_cast<const float4*>(g_q)[b * 256 + tid];
    q_s4[tid + 128] = reinterpret_cast<const float4*>(g_q)[b * 256 + tid + 128];
    __syncthreads();

    const float4* base4 = reinterpret_cast<const float4*>(
        cntx + ((size_t)b * S + (size_t)sp * CH) * H);

    float m = -1e30f, l = 0.f;
    float4 acc[8];
    #pragma unroll
    for (int j = 0; j < 8; j++) acc[j] = make_float4(0.f, 0.f, 0.f, 0.f);

    for (int r = 0; r < RPW; r += 2) {
        const size_t row0 = (size_t)(wid * RPW + r) * 256;
        const size_t row1 = row0 + 256;

        float4 v0[8], v1[8];
        #pragma unroll
        for (int j = 0; j < 8; j++) v0[j] = __ldcs(&base4[row0 + j * 32 + lane]);
        #pragma unroll
        for (int j = 0; j < 8; j++) v1[j] = __ldcs(&base4[row1 + j * 32 + lane]);

        float d0 = 0.f, d1 = 0.f;
        #pragma unroll
        for (int j = 0; j < 8; j++) {
            float4 qv = q_s4[j * 32 + lane];
            d0 = fmaf(v0[j].x, qv.x, d0); d0 = fmaf(v0[j].y, qv.y, d0);
            d0 = fmaf(v0[j].z, qv.z, d0); d0 = fmaf(v0[j].w, qv.w, d0);
            d1 = fmaf(v1[j].x, qv.x, d1); d1 = fmaf(v1[j].y, qv.y, d1);
            d1 = fmaf(v1[j].z, qv.z, d1); d1 = fmaf(v1[j].w, qv.w, d1);
        }
        #pragma unroll
        for (int off = 16; off > 0; off >>= 1) {
            d0 += __shfl_xor_sync(0xffffffffu, d0, off);
            d1 += __shfl_xor_sync(0xffffffffu, d1, off);
        }

        float mnew = fmaxf(m, fmaxf(d0, d1));
        float corr = __expf(m - mnew);
        float e0   = __expf(d0 - mnew);
        float e1   = __expf(d1 - mnew);
        l = fmaf(l, corr, e0 + e1);
        #pragma unroll
        for (int j = 0; j < 8; j++) {
            acc[j].x = fmaf(acc[j].x, corr, fmaf(e0, v0[j].x, e1 * v1[j].x));
            acc[j].y = fmaf(acc[j].y, corr, fmaf(e0, v0[j].y, e1 * v1[j].y));
            acc[j].z = fmaf(acc[j].z, corr, fmaf(e0, v0[j].z, e1 * v1[j].z));
            acc[j].w = fmaf(acc[j].w, corr, fmaf(e0, v0[j].w, e1 * v1[j].w));
        }
        m = mnew;
    }

    // ---- CTA merge of 4 warp states ----
    if (lane == 0) { mlbuf[wid][0] = m; mlbuf[wid][1] = l; }
    __syncthreads();

    float M = -1e30f;
    #pragma unroll
    for (int w = 0; w < WARPS; w++) M = fmaxf(M, mlbuf[w][0]);
    float L = 0.f;
    #pragma unroll
    for (int w = 0; w < WARPS; w++) L += mlbuf[w][1] * __expf(mlbuf[w][0] - M);

    float wi = __expf(m - M);   // this warp's rescale
    #pragma unroll
    for (int j = 0; j < 8; j++) {
        float4 a = acc[j];
        a.x *= wi; a.y *= wi; a.z *= wi; a.w *= wi;
        accbuf[wid][j * 32 + lane] = a;
    }
    __syncthreads();

    #pragma unroll
    for (int c0 = 0; c0 < 2; c0++) {
        int c = tid + c0 * 128;
        float4 s = accbuf[0][c];
        #pragma unroll
        for (int w = 1; w < WARPS; w++) {
            float4 p = accbuf[w][c];
            s.x += p.x; s.y += p.y; s.z += p.z; s.w += p.w;
        }
        g_pacc[((size_t)b * NSPLIT + sp) * 256 + c] = s;
    }
    if (tid == 0) {
        g_ml[(b * NSPLIT + sp) * 2 + 0] = M;
        g_ml[(b * NSPLIT + sp) * 2 + 1] = L;
    }
}

// ---------------------------------------------------------------------------
// Kernel 3: max-MLP combine. grid (4, B), 64 threads.
// One thread owns one output float4 column: 16 INDEPENDENT g_pacc loads,
// no cross-thread reduction, no barriers after the tiny ml stage.
// ---------------------------------------------------------------------------
__global__ __launch_bounds__(64) void combine_kernel(const float* __restrict__ h_t,
                                                     const float* __restrict__ alpha,
                                                     const float* __restrict__ beta,
                                                     float* __restrict__ out)
{
    __shared__ float ml[NSPLIT * 2];

    const int tid = threadIdx.x;
    const int b   = blockIdx.y;
    const int col = blockIdx.x * 64 + tid;   // float4 column 0..255

    if (tid < NSPLIT * 2) ml[tid] = g_ml[b * NSPLIT * 2 + tid];
    __syncthreads();

    // all 16 loads independent — issued back-to-back (256 B MLP per thread)
    float4 p[NSPLIT];
    #pragma unroll
    for (int i = 0; i < NSPLIT; i++)
        p[i] = g_pacc[((size_t)b * NSPLIT + i) * 256 + col];

    float M = -1e30f;
    #pragma unroll
    for (int i = 0; i < NSPLIT; i++) M = fmaxf(M, ml[i * 2]);
    float L = 0.f;
    #pragma unroll
    for (int i = 0; i < NSPLIT; i++) L += ml[i * 2 + 1] * __expf(ml[i * 2] - M);

    float4 o = make_float4(0.f, 0.f, 0.f, 0.f);
    #pragma unroll
    for (int i = 0; i < NSPLIT; i++) {
        float wi = __expf(ml[i * 2] - M);
        o.x = fmaf(wi, p[i].x, o.x);
        o.y = fmaf(wi, p[i].y, o.y);
        o.z = fmaf(wi, p[i].z, o.z);
        o.w = fmaf(wi, p[i].w, o.w);
    }

    float a  = alpha[0];
    float bt = beta[0] / L;
    float4 hv = reinterpret_cast<const float4*>(h_t)[b * 256 + col];
    float4 res;
    res.x = fmaf(a, hv.x, bt * o.x);
    res.y = fmaf(a, hv.y, bt * o.y);
    res.z = fmaf(a, hv.z, bt * o.z);
    res.w = fmaf(a, hv.w, bt * o.w);
    reinterpret_cast<float4*>(out)[b * 256 + col] = res;
}

// ---------------------------------------------------------------------------
extern "C" void kernel_launch(void* const* d_in, const int* in_sizes, int n_in,
                              void* d_out, int out_size)
{
    const float* h_t   = (const float*)d_in[0];
    const float* cntx  = (const float*)d_in[1];
    const float* W     = (const float*)d_in[2];
    const float* alpha = (const float*)d_in[3];
    const float* beta  = (const float*)d_in[4];
    float* out = (float*)d_out;

    qpart_kernel<<<dim3(1, KSLICES, B / BG), 256>>>(h_t, W);
    qreduce_kernel<<<B * H / 256, 256>>>();
    split_kernel<<<dim3(NSPLIT, B), 128>>>(cntx);
    combine_kernel<<<dim3(4, B), 64>>>(h_t, alpha, beta, out);
}

// round 10
// speedup vs baseline: 1.1149x; 1.1149x over previous
#include <cuda_runtime.h>

// Problem constants
#define B 32
#define S 2048
#define H 1024

// ---- split-softmax config ----
#define NSPLIT 16            // S-splits per batch
#define CH (S / NSPLIT)      // 128 rows per CTA
#define WARPS 4              // 128-thread CTAs
#define RPW (CH / WARPS)     // 32 rows per warp

// ---- q GEMV config ----
#define KSLICES 32
#define KCH (H / KSLICES)    // 32
#define BG 8

// Scratch (no cudaMalloc allowed)
__device__ float  g_qpart[KSLICES * B * H];          // 4 MB
__device__ float  g_q[B * H];                        // 128 KB
// TRANSPOSED partials: [b][col(256 float4)][split(16)]
__device__ float4 g_pacc[B * (H / 4) * NSPLIT];      // 2 MB
__device__ float  g_ml[B * NSPLIT * 2];              // (M, L) per split

// ---------------------------------------------------------------------------
// Kernel 1: partial q[b,h] = sum_{k in slice} h_t[b,k] * W[k,h]
// grid (1, KSLICES=32, B/BG=4), 256 threads.
// ---------------------------------------------------------------------------
__global__ __launch_bounds__(256) void qpart_kernel(const float* __restrict__ h_t,
                                                    const float* __restrict__ W)
{
    __shared__ float hs[BG][KCH];
    const int tid = threadIdx.x;
    const int k0  = blockIdx.y * KCH;
    const int bg  = blockIdx.z;

    {   // BG*KCH = 256 floats, one per thread
        int j  = tid >> 5;
        int kk = tid & 31;
        hs[j][kk] = h_t[(bg * BG + j) * H + k0 + kk];
    }
    __syncthreads();

    float4 acc[BG];
    #pragma unroll
    for (int j = 0; j < BG; j++) acc[j] = make_float4(0.f, 0.f, 0.f, 0.f);

    const float4* wp = reinterpret_cast<const float4*>(W) + (size_t)k0 * 256 + tid;
    #pragma unroll
    for (int kk = 0; kk < KCH; kk++) {
        float4 w = wp[(size_t)kk * 256];
        #pragma unroll
        for (int j = 0; j < BG; j++) {
            float h = hs[j][kk];
            acc[j].x = fmaf(h, w.x, acc[j].x);
            acc[j].y = fmaf(h, w.y, acc[j].y);
            acc[j].z = fmaf(h, w.z, acc[j].z);
            acc[j].w = fmaf(h, w.w, acc[j].w);
        }
    }
    float4* qp = reinterpret_cast<float4*>(g_qpart);
    #pragma unroll
    for (int j = 0; j < BG; j++)
        qp[((size_t)blockIdx.y * B + bg * BG + j) * 256 + tid] = acc[j];
}

// ---------------------------------------------------------------------------
// Kernel 1b: q = sum over KSLICES partials. grid (128), 256 threads.
// ---------------------------------------------------------------------------
__global__ __launch_bounds__(256) void qreduce_kernel()
{
    const int idx = blockIdx.x * 256 + threadIdx.x;
    float v = 0.f;
    #pragma unroll
    for (int p = 0; p < KSLICES; p++)
        v += g_qpart[(size_t)p * (B * H) + idx];
    g_q[idx] = v;
}

// ---------------------------------------------------------------------------
// Kernel 2: warp-autonomous split (R7-benched main loop, unchanged).
// grid (NSPLIT, B), 128 threads. Epilogue writes TRANSPOSED g_pacc.
// ---------------------------------------------------------------------------
__global__ void __launch_bounds__(128, 4) split_kernel(const float* __restrict__ cntx)
{
    __shared__ float  q_s[H];              // 4 KB
    __shared__ float4 accbuf[WARPS][256];  // 16 KB
    __shared__ float  mlbuf[WARPS][2];

    const int tid  = threadIdx.x;
    const int wid  = tid >> 5;
    const int lane = tid & 31;
    const int b    = blockIdx.y;
    const int sp   = blockIdx.x;

    float4* q_s4 = reinterpret_cast<float4*>(q_s);
    q_s4[tid]       = reinterpret_cast<const float4*>(g_q)[b * 256 + tid];
    q_s4[tid + 128] = reinterpret_cast<const float4*>(g_q)[b * 256 + tid + 128];
    __syncthreads();

    const float4* base4 = reinterpret_cast<const float4*>(
        cntx + ((size_t)b * S + (size_t)sp * CH) * H);

    float m = -1e30f, l = 0.f;
    float4 acc[8];
    #pragma unroll
    for (int j = 0; j < 8; j++) acc[j] = make_float4(0.f, 0.f, 0.f, 0.f);

    for (int r = 0; r < RPW; r += 2) {
        const size_t row0 = (size_t)(wid * RPW + r) * 256;
        const size_t row1 = row0 + 256;

        float4 v0[8], v1[8];
        #pragma unroll
        for (int j = 0; j < 8; j++) v0[j] = __ldcs(&base4[row0 + j * 32 + lane]);
        #pragma unroll
        for (int j = 0; j < 8; j++) v1[j] = __ldcs(&base4[row1 + j * 32 + lane]);

        float d0 = 0.f, d1 = 0.f;
        #pragma unroll
        for (int j = 0; j < 8; j++) {
            float4 qv = q_s4[j * 32 + lane];
            d0 = fmaf(v0[j].x, qv.x, d0); d0 = fmaf(v0[j].y, qv.y, d0);
            d0 = fmaf(v0[j].z, qv.z, d0); d0 = fmaf(v0[j].w, qv.w, d0);
            d1 = fmaf(v1[j].x, qv.x, d1); d1 = fmaf(v1[j].y, qv.y, d1);
            d1 = fmaf(v1[j].z, qv.z, d1); d1 = fmaf(v1[j].w, qv.w, d1);
        }
        #pragma unroll
        for (int off = 16; off > 0; off >>= 1) {
            d0 += __shfl_xor_sync(0xffffffffu, d0, off);
            d1 += __shfl_xor_sync(0xffffffffu, d1, off);
        }

        float mnew = fmaxf(m, fmaxf(d0, d1));
        float corr = __expf(m - mnew);
        float e0   = __expf(d0 - mnew);
        float e1   = __expf(d1 - mnew);
        l = fmaf(l, corr, e0 + e1);
        #pragma unroll
        for (int j = 0; j < 8; j++) {
            acc[j].x = fmaf(acc[j].x, corr, fmaf(e0, v0[j].x, e1 * v1[j].x));
            acc[j].y = fmaf(acc[j].y, corr, fmaf(e0, v0[j].y, e1 * v1[j].y));
            acc[j].z = fmaf(acc[j].z, corr, fmaf(e0, v0[j].z, e1 * v1[j].z));
            acc[j].w = fmaf(acc[j].w, corr, fmaf(e0, v0[j].w, e1 * v1[j].w));
        }
        m = mnew;
    }

    // ---- CTA merge of 4 warp states ----
    if (lane == 0) { mlbuf[wid][0] = m; mlbuf[wid][1] = l; }
    __syncthreads();

    float M = -1e30f;
    #pragma unroll
    for (int w = 0; w < WARPS; w++) M = fmaxf(M, mlbuf[w][0]);
    float L = 0.f;
    #pragma unroll
    for (int w = 0; w < WARPS; w++) L += mlbuf[w][1] * __expf(mlbuf[w][0] - M);

    float wi = __expf(m - M);   // this warp's rescale
    #pragma unroll
    for (int j = 0; j < 8; j++) {
        float4 a = acc[j];
        a.x *= wi; a.y *= wi; a.z *= wi; a.w *= wi;
        accbuf[wid][j * 32 + lane] = a;
    }
    __syncthreads();

    // transposed store: [b][col][split]
    #pragma unroll
    for (int c0 = 0; c0 < 2; c0++) {
        int c = tid + c0 * 128;
        float4 s = accbuf[0][c];
        #pragma unroll
        for (int w = 1; w < WARPS; w++) {
            float4 p = accbuf[w][c];
            s.x += p.x; s.y += p.y; s.z += p.z; s.w += p.w;
        }
        g_pacc[((size_t)b * 256 + c) * NSPLIT + sp] = s;
    }
    if (tid == 0) {
        g_ml[(b * NSPLIT + sp) * 2 + 0] = M;
        g_ml[(b * NSPLIT + sp) * 2 + 1] = L;
    }
}

// ---------------------------------------------------------------------------
// Kernel 3: combine. grid (16, B), 256 threads.
// 16-lane group owns one output column; lane = split. Coalesced 256 B
// chunk per group, every load independent, 4-level shuffle reduce.
// ---------------------------------------------------------------------------
__global__ __launch_bounds__(256) void combine_kernel(const float* __restrict__ h_t,
                                                      const float* __restrict__ alpha,
                                                      const float* __restrict__ beta,
                                                      float* __restrict__ out)
{
    __shared__ float ml[NSPLIT * 2];

    const int tid = threadIdx.x;
    const int b   = blockIdx.y;
    const int sl  = tid & 15;                     // split index (lane in group)
    const int g   = tid >> 4;                     // group 0..15
    const int col = blockIdx.x * 16 + g;          // float4 column 0..255

    if (tid < NSPLIT * 2) ml[tid] = g_ml[b * NSPLIT * 2 + tid];
    __syncthreads();

    // coalesced, independent load: group g reads 16 consecutive float4
    float4 p = g_pacc[((size_t)b * 256 + col) * NSPLIT + sl];

    float M = -1e30f;
    #pragma unroll
    for (int i = 0; i < NSPLIT; i++) M = fmaxf(M, ml[i * 2]);
    float L = 0.f;
    #pragma unroll
    for (int i = 0; i < NSPLIT; i++) L += ml[i * 2 + 1] * __expf(ml[i * 2] - M);

    float wi = __expf(ml[sl * 2] - M);
    p.x *= wi; p.y *= wi; p.z *= wi; p.w *= wi;

    // reduce across the 16-lane group
    #pragma unroll
    for (int off = 8; off > 0; off >>= 1) {
        p.x += __shfl_xor_sync(0xffffffffu, p.x, off);
        p.y += __shfl_xor_sync(0xffffffffu, p.y, off);
        p.z += __shfl_xor_sync(0xffffffffu, p.z, off);
        p.w += __shfl_xor_sync(0xffffffffu, p.w, off);
    }

    if (sl == 0) {
        float a  = alpha[0];
        float bt = beta[0] / L;
        float4 hv = reinterpret_cast<const float4*>(h_t)[b * 256 + col];
        float4 res;
        res.x = fmaf(a, hv.x, bt * p.x);
        res.y = fmaf(a, hv.y, bt * p.y);
        res.z = fmaf(a, hv.z, bt * p.z);
        res.w = fmaf(a, hv.w, bt * p.w);
        reinterpret_cast<float4*>(out)[b * 256 + col] = res;
    }
}

// ---------------------------------------------------------------------------
extern "C" void kernel_launch(void* const* d_in, const int* in_sizes, int n_in,
                              void* d_out, int out_size)
{
    const float* h_t   = (const float*)d_in[0];
    const float* cntx  = (const float*)d_in[1];
    const float* W     = (const float*)d_in[2];
    const float* alpha = (const float*)d_in[3];
    const float* beta  = (const float*)d_in[4];
    float* out = (float*)d_out;

    qpart_kernel<<<dim3(1, KSLICES, B / BG), 256>>>(h_t, W);
    qreduce_kernel<<<B * H / 256, 256>>>();
    split_kernel<<<dim3(NSPLIT, B), 128>>>(cntx);
    combine_kernel<<<dim3(16, B), 256>>>(h_t, alpha, beta, out);
}